// round 1
// baseline (speedup 1.0000x reference)
#include <cuda_runtime.h>

// CapsuleConv2d fused kernel.
// Problem constants: N=4, C=64, H=W=32, O=8, L=16, G=8, P(IN_LEN)=8, F=G*9=72,
// Ho=Wo=32, NUM_ITERS=3. One thread per output element (pos, o, l).
//
// CTA: 8 consecutive positions in one row x 16 l-lanes = 128 threads.
// grid = (512 position-tiles, 8 o).
//
// Shared (floats):
//   w_s   [72][16 l][8 p]  float2-swizzled   : 9216
//   win_s [8 pos][72 f][8 p]                 : 4608
//   spri  [8 pos][72 f][16 l] stride 17      : 9792
//   sprob [8 pos][72 f]                      : 576
//   souts [8 pos][16 l]                      : 128
#define SM_FLOATS 24320

__global__ __launch_bounds__(128)
void caps_kernel(const float* __restrict__ x, const float* __restrict__ w,
                 float* __restrict__ out)
{
    extern __shared__ float sm[];
    float* w_s   = sm;            // 9216
    float* win_s = sm + 9216;     // 4608
    float* spri  = sm + 13824;    // 8*72*17 = 9792
    float* sprob = sm + 23616;    // 576
    float* souts = sm + 24192;    // 128

    const int tid = threadIdx.x;
    const int l   = tid & 15;     // capsule-out index
    const int pos = tid >> 4;     // position within tile (0..7)

    const int o    = blockIdx.y;
    const int tile = blockIdx.x;        // 0..511
    const int n    = tile >> 7;         // 128 tiles per image
    const int rem  = tile & 127;
    const int y    = rem >> 2;          // output row
    const int x0   = (rem & 3) << 3;    // output col base

    // ---- stage weight slice for this o into shared (float2 bank swizzle) ----
    {
        const float2* gw = (const float2*)(w + o * 9216);
        float2* sw = (float2*)w_s;
        #pragma unroll
        for (int i = 0; i < 36; i++) {
            int idx = tid + i * 128;            // 0..4607 float2s
            int f   = idx >> 6;
            int r   = idx & 63;
            int ll  = r >> 2;
            int p2  = r & 3;
            int dst = f * 64 + ll * 4 + (p2 ^ ((ll >> 2) & 3));
            sw[dst] = gw[idx];
        }
    }
    // ---- stage win patches: win[pos][f=g*9+kh*3+kw][p] = x[n, g*8+p, y+kh-1, x0+pos+kw-1]
    for (int idx = tid; idx < 4608; idx += 128) {
        int ppos = idx & 7;
        int fp   = idx >> 3;            // f*8 + p
        int f    = fp >> 3;
        int p    = fp & 7;
        int g    = f / 9;
        int kpos = f - g * 9;
        int kh   = kpos / 3;
        int kw   = kpos - kh * 3;
        int iy = y + kh - 1;
        int ix = x0 + ppos + kw - 1;
        float v = 0.0f;
        if ((unsigned)iy < 32u && (unsigned)ix < 32u) {
            int c = g * 8 + p;
            v = x[((n * 64 + c) * 32 + iy) * 32 + ix];
        }
        win_s[ppos * 576 + fp] = v;
    }
    __syncthreads();

    // ---- priors[f] = dot8(w[o,f,l,:], win[pos,f,:]) ----
    float pri[72];
    {
        const int sw_ = (l >> 2) & 3;
        const float2* wv = (const float2*)w_s + l * 4;
        const float2* xv = (const float2*)(win_s + pos * 576);
        const int o0 = 0 ^ sw_, o1 = 1 ^ sw_, o2 = 2 ^ sw_, o3 = 3 ^ sw_;
        #pragma unroll
        for (int f = 0; f < 72; f++) {
            float2 a0 = wv[f * 64 + o0];
            float2 a1 = wv[f * 64 + o1];
            float2 a2 = wv[f * 64 + o2];
            float2 a3 = wv[f * 64 + o3];
            float2 b0 = xv[f * 4 + 0];
            float2 b1 = xv[f * 4 + 1];
            float2 b2 = xv[f * 4 + 2];
            float2 b3 = xv[f * 4 + 3];
            pri[f] = a0.x * b0.x + a0.y * b0.y
                   + a1.x * b1.x + a1.y * b1.y
                   + a2.x * b2.x + a2.y * b2.y
                   + a3.x * b3.x + a3.y * b3.y;
        }
    }

    // ---- stash priors for the delta reduction; init probs = 1 ----
    {
        float* pr = spri + (pos * 72) * 17 + l;
        #pragma unroll
        for (int f = 0; f < 72; f++) pr[f * 17] = pri[f];
        #pragma unroll
        for (int j = 0; j < 5; j++) {
            if (j < 4 || l < 8) sprob[pos * 72 + l + 16 * j] = 1.0f;
        }
    }
    __syncwarp();

    // ---- dynamic routing: 3 iterations ----
    float outv = 0.0f;
    for (int r = 0; r < 3; r++) {
        float acc = 0.0f;
        if (r == 0) {
            #pragma unroll
            for (int f = 0; f < 72; f++) acc += pri[f];
        } else {
            #pragma unroll
            for (int f = 0; f < 72; f++) acc += sprob[pos * 72 + f] * pri[f];
        }
        float s = acc * 0.125f;               // mean over G folded into flat sum
        float sq = s * s;                     // ||s||^2 over the 16 l-lanes
        #pragma unroll
        for (int d = 8; d >= 1; d >>= 1)
            sq += __shfl_xor_sync(0xffffffffu, sq, d);
        float factor = sqrtf(sq) / (1.0f + sq);   // sq/(1+sq)/sqrt(sq)
        outv = s * factor;

        if (r < 2) {
            souts[pos * 16 + l] = outv;
            __syncwarp();
            const float4* sov = (const float4*)(souts + pos * 16);
            float4 s0 = sov[0], s1 = sov[1], s2 = sov[2], s3 = sov[3];
            // lane l owns f = l, l+16, l+32, l+48 (+ l+64 if l<8)
            #pragma unroll
            for (int j = 0; j < 5; j++) {
                if (j < 4 || l < 8) {
                    const float* p2 = spri + (pos * 72 + l + 16 * j) * 17;
                    float d =
                        p2[0]  * s0.x + p2[1]  * s0.y + p2[2]  * s0.z + p2[3]  * s0.w +
                        p2[4]  * s1.x + p2[5]  * s1.y + p2[6]  * s1.z + p2[7]  * s1.w +
                        p2[8]  * s2.x + p2[9]  * s2.y + p2[10] * s2.z + p2[11] * s2.w +
                        p2[12] * s3.x + p2[13] * s3.y + p2[14] * s3.z + p2[15] * s3.w;
                    sprob[pos * 72 + l + 16 * j] += __expf(d);
                }
            }
            __syncwarp();
        }
    }

    // out[n][o*16+l][y][x0+pos]
    out[((n * 128 + o * 16 + l) * 32 + y) * 32 + x0 + pos] = outv;
}

extern "C" void kernel_launch(void* const* d_in, const int* in_sizes, int n_in,
                              void* d_out, int out_size)
{
    (void)in_sizes; (void)n_in; (void)out_size;
    const float* x = (const float*)d_in[0];
    const float* w = (const float*)d_in[1];
    float* out     = (float*)d_out;

    cudaFuncSetAttribute(caps_kernel, cudaFuncAttributeMaxDynamicSharedMemorySize,
                         SM_FLOATS * 4);
    dim3 grid(512, 8);
    caps_kernel<<<grid, 128, SM_FLOATS * 4>>>(x, w, out);
}

// round 2
// speedup vs baseline: 1.0682x; 1.0682x over previous
#include <cuda_runtime.h>

// CapsuleConv2d fused kernel, round 2: full 128-bit vectorization of shared traffic.
// N=4, C=64, H=W=32, O=8, L=16, G=8, P=8, F=72, Ho=Wo=32, NUM_ITERS=3.
// CTA: 8 positions x 16 l = 128 threads. grid = (512, 8 o).
//
// Shared layout (floats):
//   w_s   [72 f][16 l][2 slot] float4, slot swizzled by s ^ ((l>>2)&1) : 9216
//   win_s [8 pos](stride 580)[72 f][8 p]                               : 4640
//   spri  [8 pos](stride 1456)[72 f](stride 20)[16 l]                  : 11648
//   sprob [8 pos][72 f]                                                : 576
//   souts [8 pos][16 l]                                                : 128
#define W_S_OFF    0
#define WIN_OFF    9216
#define WIN_STRIDE 580
#define SPRI_OFF   13856
#define SPRI_POS   1456
#define SPRI_F     20
#define SPROB_OFF  25504
#define SOUT_OFF   26080
#define SM_FLOATS  26208

__global__ __launch_bounds__(128)
void caps_kernel(const float* __restrict__ x, const float* __restrict__ w,
                 float* __restrict__ out)
{
    extern __shared__ float sm[];
    float* w_s   = sm + W_S_OFF;
    float* win_s = sm + WIN_OFF;
    float* spri  = sm + SPRI_OFF;
    float* sprob = sm + SPROB_OFF;
    float* souts = sm + SOUT_OFF;

    const int tid = threadIdx.x;
    const int l   = tid & 15;
    const int pos = tid >> 4;

    const int o    = blockIdx.y;
    const int tile = blockIdx.x;
    const int n    = tile >> 7;
    const int rem  = tile & 127;
    const int y    = rem >> 2;
    const int x0   = (rem & 3) << 3;

    // ---- stage weights: float4 granularity, slot swizzle ----
    {
        const float4* gw = (const float4*)(w + o * 9216);   // 2304 float4s
        float4* sw = (float4*)w_s;
        #pragma unroll
        for (int i = 0; i < 18; i++) {
            int idx = tid + i * 128;
            int f   = idx >> 5;
            int r   = idx & 31;
            int ll  = r >> 1;
            int s   = r & 1;
            sw[f * 32 + ll * 2 + (s ^ ((ll >> 2) & 1))] = gw[idx];
        }
    }
    // ---- stage win patches (stride 580 per pos) ----
    for (int idx = tid; idx < 4608; idx += 128) {
        int ppos = idx & 7;
        int fp   = idx >> 3;
        int f    = fp >> 3;
        int p    = fp & 7;
        int g    = f / 9;
        int kpos = f - g * 9;
        int kh   = kpos / 3;
        int kw   = kpos - kh * 3;
        int iy = y + kh - 1;
        int ix = x0 + ppos + kw - 1;
        float v = 0.0f;
        if ((unsigned)iy < 32u && (unsigned)ix < 32u) {
            v = x[((n * 64 + g * 8 + p) * 32 + iy) * 32 + ix];
        }
        win_s[ppos * WIN_STRIDE + fp] = v;
    }
    __syncthreads();

    // ---- priors + inline stash to spri ----
    float pri[72];
    {
        const int b = (l >> 2) & 1;
        const float4* wlo4 = (const float4*)w_s + l * 2 + b;
        const float4* whi4 = (const float4*)w_s + l * 2 + (1 ^ b);
        const float4* xv4  = (const float4*)(win_s + pos * WIN_STRIDE);
        float* pr = spri + pos * SPRI_POS + l;
        #pragma unroll
        for (int f = 0; f < 72; f++) {
            float4 a0 = wlo4[f * 32];
            float4 a1 = whi4[f * 32];
            float4 b0 = xv4[f * 2];
            float4 b1 = xv4[f * 2 + 1];
            float v = a0.x * b0.x + a0.y * b0.y + a0.z * b0.z + a0.w * b0.w
                    + a1.x * b1.x + a1.y * b1.y + a1.z * b1.z + a1.w * b1.w;
            pri[f] = v;
            pr[f * SPRI_F] = v;
        }
    }
    __syncwarp();

    // ---- dynamic routing (probs live in owner-lane registers) ----
    float pb0 = 1.0f, pb1 = 1.0f, pb2 = 1.0f, pb3 = 1.0f, pb4 = 1.0f;
    float outv = 0.0f;
    #pragma unroll
    for (int r = 0; r < 3; r++) {
        float acc = 0.0f;
        if (r == 0) {
            #pragma unroll
            for (int f = 0; f < 72; f++) acc += pri[f];
        } else {
            const float4* pr4 = (const float4*)(sprob + pos * 72);
            #pragma unroll
            for (int i = 0; i < 18; i++) {
                float4 p = pr4[i];
                acc += p.x * pri[4 * i] + p.y * pri[4 * i + 1]
                     + p.z * pri[4 * i + 2] + p.w * pri[4 * i + 3];
            }
        }
        float s = acc * 0.125f;
        float sq = s * s;
        #pragma unroll
        for (int d = 8; d >= 1; d >>= 1)
            sq += __shfl_xor_sync(0xffffffffu, sq, d);
        float factor = sqrtf(sq) / (1.0f + sq);
        outv = s * factor;

        if (r < 2) {
            souts[pos * 16 + l] = outv;
            __syncwarp();
            const float4* sov = (const float4*)(souts + pos * 16);
            float4 s0 = sov[0], s1 = sov[1], s2 = sov[2], s3 = sov[3];
            // lane l owns f = l + 16j
            #pragma unroll
            for (int j = 0; j < 5; j++) {
                if (j < 4 || l < 8) {
                    const float4* pp = (const float4*)(spri + pos * SPRI_POS + (l + 16 * j) * SPRI_F);
                    float4 q0 = pp[0], q1 = pp[1], q2 = pp[2], q3 = pp[3];
                    float d = q0.x * s0.x + q0.y * s0.y + q0.z * s0.z + q0.w * s0.w
                            + q1.x * s1.x + q1.y * s1.y + q1.z * s1.z + q1.w * s1.w
                            + q2.x * s2.x + q2.y * s2.y + q2.z * s2.z + q2.w * s2.w
                            + q3.x * s3.x + q3.y * s3.y + q3.z * s3.z + q3.w * s3.w;
                    float e = __expf(d);
                    float nb;
                    if (j == 0)      { pb0 += e; nb = pb0; }
                    else if (j == 1) { pb1 += e; nb = pb1; }
                    else if (j == 2) { pb2 += e; nb = pb2; }
                    else if (j == 3) { pb3 += e; nb = pb3; }
                    else             { pb4 += e; nb = pb4; }
                    sprob[pos * 72 + l + 16 * j] = nb;
                }
            }
            __syncwarp();
        }
    }

    out[((n * 128 + o * 16 + l) * 32 + y) * 32 + x0 + pos] = outv;
}

extern "C" void kernel_launch(void* const* d_in, const int* in_sizes, int n_in,
                              void* d_out, int out_size)
{
    (void)in_sizes; (void)n_in; (void)out_size;
    const float* x = (const float*)d_in[0];
    const float* w = (const float*)d_in[1];
    float* out     = (float*)d_out;

    cudaFuncSetAttribute(caps_kernel, cudaFuncAttributeMaxDynamicSharedMemorySize,
                         SM_FLOATS * 4);
    dim3 grid(512, 8);
    caps_kernel<<<grid, 128, SM_FLOATS * 4>>>(x, w, out);
}

// round 4
// speedup vs baseline: 1.3758x; 1.2880x over previous
#include <cuda_runtime.h>

// CapsuleConv2d fused kernel, round 3 (resubmit after infra failure):
// phase-overlaid shared memory -> 4 CTAs/SM.
// N=4, C=64, H=W=32, O=8, L=16, G=8, P=8, F=72, Ho=Wo=32, NUM_ITERS=3.
// CTA: 8 positions x 16 l = 128 threads. grid = (512, 8 o).
//
// Shared (floats), two overlaid phases, total 13856 floats = 54.1 KB:
//  phase 1 (staging + priors):
//   w_s   [72 f][16 l][2 slot] float4, slot ^ ((l>>2)&1)   @ 0      (9216)
//   win_s [8 pos](stride 580)[72 f][8 p]                   @ 9216   (4640)
//  phase 2 (routing) overlays phase 1:
//   spri  [8 pos](stride 1456)[72 f](stride 20)[16 l]      @ 0      (11648)
//   sprob [8 pos](stride 80)[72 f]                         @ 11648  (640)
//   souts [8 pos][16 l]                                    @ 12288  (128)
#define W_S_OFF     0
#define WIN_OFF     9216
#define WIN_STRIDE  580
#define SPRI_OFF    0
#define SPRI_POS    1456
#define SPRI_F      20
#define SPROB_OFF   11648
#define SPROB_POS   80
#define SOUT_OFF    12288
#define SM_FLOATS   13856

__global__ __launch_bounds__(128, 4)
void caps_kernel(const float* __restrict__ x, const float* __restrict__ w,
                 float* __restrict__ out)
{
    extern __shared__ float sm[];
    float* w_s   = sm + W_S_OFF;
    float* win_s = sm + WIN_OFF;
    float* spri  = sm + SPRI_OFF;
    float* sprob = sm + SPROB_OFF;
    float* souts = sm + SOUT_OFF;

    const int tid = threadIdx.x;
    const int l   = tid & 15;
    const int pos = tid >> 4;

    const int o    = blockIdx.y;
    const int tile = blockIdx.x;
    const int n    = tile >> 7;
    const int rem  = tile & 127;
    const int y    = rem >> 2;
    const int x0   = (rem & 3) << 3;

    // ---- phase 1a: stage weights (float4, slot swizzle) ----
    {
        const float4* gw = (const float4*)(w + o * 9216);   // 2304 float4s
        float4* sw = (float4*)w_s;
        #pragma unroll
        for (int i = 0; i < 18; i++) {
            int idx = tid + i * 128;
            int f   = idx >> 5;
            int r   = idx & 31;
            int ll  = r >> 1;
            int s   = r & 1;
            sw[f * 32 + ll * 2 + (s ^ ((ll >> 2) & 1))] = gw[idx];
        }
    }
    // ---- phase 1b: stage win patches ----
    for (int idx = tid; idx < 4608; idx += 128) {
        int ppos = idx & 7;
        int fp   = idx >> 3;
        int f    = fp >> 3;
        int p    = fp & 7;
        int g    = f / 9;
        int kpos = f - g * 9;
        int kh   = kpos / 3;
        int kw   = kpos - kh * 3;
        int iy = y + kh - 1;
        int ix = x0 + ppos + kw - 1;
        float v = 0.0f;
        if ((unsigned)iy < 32u && (unsigned)ix < 32u) {
            v = x[((n * 64 + g * 8 + p) * 32 + iy) * 32 + ix];
        }
        win_s[ppos * WIN_STRIDE + fp] = v;
    }
    __syncthreads();

    // ---- phase 1c: priors into registers ----
    float pri[72];
    {
        const int b = (l >> 2) & 1;
        const float4* wlo4 = (const float4*)w_s + l * 2 + b;
        const float4* whi4 = (const float4*)w_s + l * 2 + (1 ^ b);
        const float4* xv4  = (const float4*)(win_s + pos * WIN_STRIDE);
        #pragma unroll
        for (int f = 0; f < 72; f++) {
            float4 a0 = wlo4[f * 32];
            float4 a1 = whi4[f * 32];
            float4 b0 = xv4[f * 2];
            float4 b1 = xv4[f * 2 + 1];
            pri[f] = a0.x * b0.x + a0.y * b0.y + a0.z * b0.z + a0.w * b0.w
                   + a1.x * b1.x + a1.y * b1.y + a1.z * b1.z + a1.w * b1.w;
        }
    }

    // ---- phase boundary: w_s/win_s dead, overlay becomes live ----
    __syncthreads();

    {
        float* pr = spri + pos * SPRI_POS + l;
        #pragma unroll
        for (int f = 0; f < 72; f++) pr[f * SPRI_F] = pri[f];
    }
    __syncwarp();

    // ---- phase 2: dynamic routing (probs in owner-lane registers) ----
    float pb0 = 1.0f, pb1 = 1.0f, pb2 = 1.0f, pb3 = 1.0f, pb4 = 1.0f;
    float outv = 0.0f;
    #pragma unroll
    for (int r = 0; r < 3; r++) {
        float acc = 0.0f;
        if (r == 0) {
            #pragma unroll
            for (int f = 0; f < 72; f++) acc += pri[f];
        } else {
            const float4* pr4 = (const float4*)(sprob + pos * SPROB_POS);
            #pragma unroll
            for (int i = 0; i < 18; i++) {
                float4 p = pr4[i];
                acc += p.x * pri[4 * i] + p.y * pri[4 * i + 1]
                     + p.z * pri[4 * i + 2] + p.w * pri[4 * i + 3];
            }
        }
        float s = acc * 0.125f;
        float sq = s * s;
        #pragma unroll
        for (int d = 8; d >= 1; d >>= 1)
            sq += __shfl_xor_sync(0xffffffffu, sq, d);
        float factor = sqrtf(sq) / (1.0f + sq);
        outv = s * factor;

        if (r < 2) {
            souts[pos * 16 + l] = outv;
            __syncwarp();
            const float4* sov = (const float4*)(souts + pos * 16);
            float4 s0 = sov[0], s1 = sov[1], s2 = sov[2], s3 = sov[3];
            // lane l owns f = l + 16j
            #pragma unroll
            for (int j = 0; j < 5; j++) {
                if (j < 4 || l < 8) {
                    const float4* pp = (const float4*)(spri + pos * SPRI_POS + (l + 16 * j) * SPRI_F);
                    float4 q0 = pp[0], q1 = pp[1], q2 = pp[2], q3 = pp[3];
                    float d = q0.x * s0.x + q0.y * s0.y + q0.z * s0.z + q0.w * s0.w
                            + q1.x * s1.x + q1.y * s1.y + q1.z * s1.z + q1.w * s1.w
                            + q2.x * s2.x + q2.y * s2.y + q2.z * s2.z + q2.w * s2.w
                            + q3.x * s3.x + q3.y * s3.y + q3.z * s3.z + q3.w * s3.w;
                    float e = __expf(d);
                    float nb;
                    if (j == 0)      { pb0 += e; nb = pb0; }
                    else if (j == 1) { pb1 += e; nb = pb1; }
                    else if (j == 2) { pb2 += e; nb = pb2; }
                    else if (j == 3) { pb3 += e; nb = pb3; }
                    else             { pb4 += e; nb = pb4; }
                    sprob[pos * SPROB_POS + l + 16 * j] = nb;
                }
            }
            __syncwarp();
        }
    }

    out[((n * 128 + o * 16 + l) * 32 + y) * 32 + x0 + pos] = outv;
}

extern "C" void kernel_launch(void* const* d_in, const int* in_sizes, int n_in,
                              void* d_out, int out_size)
{
    (void)in_sizes; (void)n_in; (void)out_size;
    const float* x = (const float*)d_in[0];
    const float* w = (const float*)d_in[1];
    float* out     = (float*)d_out;

    cudaFuncSetAttribute(caps_kernel, cudaFuncAttributeMaxDynamicSharedMemorySize,
                         SM_FLOATS * 4);
    dim3 grid(512, 8);
    caps_kernel<<<grid, 128, SM_FLOATS * 4>>>(x, w, out);
}

// round 5
// speedup vs baseline: 1.7755x; 1.2906x over previous
#include <cuda_runtime.h>

// CapsuleConv2d fused kernel, round 5: 2 positions per thread (weight-register reuse).
// N=4, C=64, H=W=32, O=8, L=16, G=8, P=8, F=72, Ho=Wo=32, NUM_ITERS=3.
// CTA: 128 threads = 8 ph x 16 l; thread handles posA=ph, posB=ph+8 (16-pos tile).
// grid = (256 tiles, 8 o).
//
// Shared (floats), phase-overlaid, total 24832 floats = 97 KB:
//  phase 1: w_s [72][16 l][2 slot] f4 swizzled  @0     (9216)
//           win_s [16 pos](stride 580)[72 f][8 p] @9216 (9280)
//  phase 2: spri [16 pos](1456)[72 f](20)[16 l] @0     (23296)
//           sprob[16 pos](80)[72 f]             @23296 (1280)
//           souts[16 pos][16 l]                 @24576 (256)
#define W_S_OFF     0
#define WIN_OFF     9216
#define WIN_STRIDE  580
#define SPRI_OFF    0
#define SPRI_POS    1456
#define SPRI_F      20
#define SPROB_OFF   23296
#define SPROB_POS   80
#define SOUT_OFF    24576
#define SM_FLOATS   24832

__device__ __forceinline__ float dot4(float4 a, float4 b) {
    return a.x * b.x + a.y * b.y + a.z * b.z + a.w * b.w;
}

__global__ __launch_bounds__(128, 2)
void caps_kernel(const float* __restrict__ x, const float* __restrict__ w,
                 float* __restrict__ out)
{
    extern __shared__ float sm[];
    float* w_s   = sm + W_S_OFF;
    float* win_s = sm + WIN_OFF;
    float* spri  = sm + SPRI_OFF;
    float* sprob = sm + SPROB_OFF;
    float* souts = sm + SOUT_OFF;

    const int tid = threadIdx.x;
    const int l   = tid & 15;
    const int ph  = tid >> 4;           // 0..7
    const int posA = ph, posB = ph + 8;

    const int o    = blockIdx.y;
    const int tile = blockIdx.x;        // 0..255
    const int n    = tile >> 6;         // 64 tiles per image
    const int rem  = tile & 63;
    const int y    = rem >> 1;          // output row
    const int x0   = (rem & 1) << 4;    // 0 or 16

    // ---- phase 1a: stage weights (float4, slot swizzle) ----
    {
        const float4* gw = (const float4*)(w + o * 9216);   // 2304 float4s
        float4* sw = (float4*)w_s;
        #pragma unroll
        for (int i = 0; i < 18; i++) {
            int idx = tid + i * 128;
            int f   = idx >> 5;
            int r   = idx & 31;
            int ll  = r >> 1;
            int s   = r & 1;
            sw[f * 32 + ll * 2 + (s ^ ((ll >> 2) & 1))] = gw[idx];
        }
    }
    // ---- phase 1b: stage win patches; thread -> (ppos, p), f fully unrolled ----
    {
        const int ppos = (tid & 7) | ((tid & 64) >> 3);   // warp covers 8 ppos x 4 p
        const int p    = (tid >> 3) & 7;
        const int xb   = x0 + ppos - 1;
        bool py[3], px[3];
        #pragma unroll
        for (int k = 0; k < 3; k++) {
            py[k] = (unsigned)(y + k - 1) < 32u;
            px[k] = (unsigned)(xb + k) < 32u;
        }
        const float* xpb = x + ((n * 64 + p) * 32 + (y - 1)) * 32 + xb;
        float* wd = win_s + ppos * WIN_STRIDE + p;
        #pragma unroll
        for (int g = 0; g < 8; g++) {
            #pragma unroll
            for (int kh = 0; kh < 3; kh++) {
                #pragma unroll
                for (int kw = 0; kw < 3; kw++) {
                    float v = 0.0f;
                    if (py[kh] & px[kw])
                        v = xpb[g * 8192 + kh * 32 + kw];
                    wd[(g * 9 + kh * 3 + kw) * 8] = v;
                }
            }
        }
    }
    __syncthreads();

    // ---- phase 1c: priors for both positions (weight regs reused) ----
    float pa[72], pb[72];
    {
        const int b = (l >> 2) & 1;
        const float4* wlo4 = (const float4*)w_s + l * 2 + b;
        const float4* whi4 = (const float4*)w_s + l * 2 + (1 ^ b);
        const float4* xa4  = (const float4*)win_s + posA * (WIN_STRIDE / 4);
        const float4* xb4  = (const float4*)win_s + posB * (WIN_STRIDE / 4);
        #pragma unroll
        for (int f = 0; f < 72; f++) {
            float4 a0 = wlo4[f * 32];
            float4 a1 = whi4[f * 32];
            float4 A0 = xa4[f * 2], A1 = xa4[f * 2 + 1];
            float4 B0 = xb4[f * 2], B1 = xb4[f * 2 + 1];
            pa[f] = dot4(a0, A0) + dot4(a1, A1);
            pb[f] = dot4(a0, B0) + dot4(a1, B1);
        }
    }

    // ---- phase boundary: w_s/win_s dead, overlay becomes live ----
    __syncthreads();

    {
        float* prA = spri + posA * SPRI_POS + l;
        float* prB = spri + posB * SPRI_POS + l;
        #pragma unroll
        for (int f = 0; f < 72; f++) {
            prA[f * SPRI_F] = pa[f];
            prB[f * SPRI_F] = pb[f];
        }
    }
    __syncwarp();

    // ---- phase 2: dynamic routing for both positions ----
    float pA0 = 1.0f, pA1 = 1.0f, pA2 = 1.0f, pA3 = 1.0f, pA4 = 1.0f;
    float pB0 = 1.0f, pB1 = 1.0f, pB2 = 1.0f, pB3 = 1.0f, pB4 = 1.0f;
    float outA = 0.0f, outB = 0.0f;
    #pragma unroll
    for (int r = 0; r < 3; r++) {
        float accA = 0.0f, accB = 0.0f;
        if (r == 0) {
            #pragma unroll
            for (int f = 0; f < 72; f++) { accA += pa[f]; accB += pb[f]; }
        } else {
            const float4* prA4 = (const float4*)(sprob + posA * SPROB_POS);
            const float4* prB4 = (const float4*)(sprob + posB * SPROB_POS);
            #pragma unroll
            for (int i = 0; i < 18; i++) {
                float4 qa = prA4[i];
                float4 qb = prB4[i];
                accA += qa.x * pa[4*i] + qa.y * pa[4*i+1] + qa.z * pa[4*i+2] + qa.w * pa[4*i+3];
                accB += qb.x * pb[4*i] + qb.y * pb[4*i+1] + qb.z * pb[4*i+2] + qb.w * pb[4*i+3];
            }
        }
        float sA = accA * 0.125f, sB = accB * 0.125f;
        float sqA = sA * sA, sqB = sB * sB;
        #pragma unroll
        for (int d = 8; d >= 1; d >>= 1) {
            sqA += __shfl_xor_sync(0xffffffffu, sqA, d);
            sqB += __shfl_xor_sync(0xffffffffu, sqB, d);
        }
        outA = sA * (sqrtf(sqA) / (1.0f + sqA));
        outB = sB * (sqrtf(sqB) / (1.0f + sqB));

        if (r < 2) {
            souts[posA * 16 + l] = outA;
            souts[posB * 16 + l] = outB;
            __syncwarp();
            const float4* svA = (const float4*)(souts + posA * 16);
            const float4* svB = (const float4*)(souts + posB * 16);
            float4 a0 = svA[0], a1 = svA[1], a2 = svA[2], a3 = svA[3];
            float4 b0 = svB[0], b1 = svB[1], b2 = svB[2], b3 = svB[3];
            #pragma unroll
            for (int j = 0; j < 5; j++) {
                if (j < 4 || l < 8) {
                    const int fo = l + 16 * j;
                    const float4* qpA = (const float4*)(spri + posA * SPRI_POS + fo * SPRI_F);
                    float dA = dot4(qpA[0], a0) + dot4(qpA[1], a1)
                             + dot4(qpA[2], a2) + dot4(qpA[3], a3);
                    float eA = __expf(dA);
                    float nA;
                    if (j == 0)      { pA0 += eA; nA = pA0; }
                    else if (j == 1) { pA1 += eA; nA = pA1; }
                    else if (j == 2) { pA2 += eA; nA = pA2; }
                    else if (j == 3) { pA3 += eA; nA = pA3; }
                    else             { pA4 += eA; nA = pA4; }
                    sprob[posA * SPROB_POS + fo] = nA;

                    const float4* qpB = (const float4*)(spri + posB * SPRI_POS + fo * SPRI_F);
                    float dB = dot4(qpB[0], b0) + dot4(qpB[1], b1)
                             + dot4(qpB[2], b2) + dot4(qpB[3], b3);
                    float eB = __expf(dB);
                    float nB;
                    if (j == 0)      { pB0 += eB; nB = pB0; }
                    else if (j == 1) { pB1 += eB; nB = pB1; }
                    else if (j == 2) { pB2 += eB; nB = pB2; }
                    else if (j == 3) { pB3 += eB; nB = pB3; }
                    else             { pB4 += eB; nB = pB4; }
                    sprob[posB * SPROB_POS + fo] = nB;
                }
            }
            __syncwarp();
        }
    }

    float* ob = out + ((n * 128 + o * 16 + l) * 32 + y) * 32 + x0;
    ob[posA] = outA;
    ob[posB] = outB;
}

extern "C" void kernel_launch(void* const* d_in, const int* in_sizes, int n_in,
                              void* d_out, int out_size)
{
    (void)in_sizes; (void)n_in; (void)out_size;
    const float* x = (const float*)d_in[0];
    const float* w = (const float*)d_in[1];
    float* out     = (float*)d_out;

    cudaFuncSetAttribute(caps_kernel, cudaFuncAttributeMaxDynamicSharedMemorySize,
                         SM_FLOATS * 4);
    dim3 grid(256, 8);
    caps_kernel<<<grid, 128, SM_FLOATS * 4>>>(x, w, out);
}